// round 1
// baseline (speedup 1.0000x reference)
#include <cuda_runtime.h>
#include <math.h>

#define BB 2048
#define SS 23
#define DD 768
#define HH 8
#define HDD 96
#define LL 50
#define NT 184      // SS*HH (query,head) pairs
#define NTP 192     // padded to multiple of 64
#define KA 6912     // 9*768 = HH*DD + DD (u concat cls_sum)
#define NL 64       // padded logits
#define NSPLIT 9

// ---------------- scratch (static device globals; no allocation) ----------------
__device__ float g_qconst[SS*DD];          // q at missing positions (batch-constant)
__device__ float g_sproj[NTP*DD];          // Wk_h^T q_const, padded rows zeroed
__device__ float g_c0[NTP];                // q_const . bk
__device__ float g_M[LL*DD];               // pred_w @ out_proj_w
__device__ float g_Wbig[KA*NL];            // [F | pred_w] as [K][N]
__device__ float g_bvM[NL];                // M . bv
__device__ float g_boutP[NL];              // pred_w . out_proj_b
__device__ float g_msumP[NL];              // (sum_s missing_table) . pred_w
__device__ float g_scores[BB*SS*NTP];      // raw scores, 36 MB
__device__ float g_A[(size_t)BB*KA];       // [u(6144) | cls_sum(768)] per batch
__device__ float g_P[(size_t)NSPLIT*BB*NL];// split-K partials

// ---------------- precompute kernels ----------------
__global__ void p1_qconst(const float* __restrict__ mt, const float* __restrict__ W,
                          const float* __restrict__ bias) {
    int idx = blockIdx.x*256 + threadIdx.x;
    if (idx >= SS*DD) return;
    int sq = idx / DD, c = idx % DD;
    const float* m = mt + sq*DD;
    const float* w = W + (size_t)c*DD;
    float acc = bias[c];
    for (int k = 0; k < DD; k++) acc += m[k]*w[k];
    g_qconst[idx] = acc * rsqrtf((float)HDD);
}

__global__ void p2_sproj(const float* __restrict__ W) {
    int idx = blockIdx.x*256 + threadIdx.x;
    if (idx >= NTP*DD) return;
    int t = idx / DD, d = idx % DD;
    if (t >= NT) { g_sproj[idx] = 0.f; return; }
    int sq = t / HH, h = t % HH;
    const float* q = g_qconst + sq*DD + h*HDD;
    float acc = 0.f;
    for (int j = 0; j < HDD; j++)
        acc += q[j] * W[(size_t)(DD + h*HDD + j)*DD + d];
    g_sproj[idx] = acc;
}

__global__ void p3_M(const float* __restrict__ pw, const float* __restrict__ ow) {
    int idx = blockIdx.x*256 + threadIdx.x;
    if (idx >= LL*DD) return;
    int l = idx / DD, d = idx % DD;
    float acc = 0.f;
    for (int j = 0; j < DD; j++) acc += pw[l*DD + j] * ow[(size_t)j*DD + d];
    g_M[idx] = acc;
}

__global__ void p4_wbig(const float* __restrict__ W, const float* __restrict__ pw) {
    int idx = blockIdx.x*256 + threadIdx.x;
    if (idx >= KA*NL) return;
    int k = idx / NL, l = idx % NL;
    float v = 0.f;
    if (l < LL) {
        if (k < HH*DD) {
            int h = k / DD, d = k % DD;
            float acc = 0.f;
            for (int t = 0; t < HDD; t++)
                acc += g_M[l*DD + h*HDD + t] * W[(size_t)(2*DD + h*HDD + t)*DD + d];
            v = acc;
        } else {
            v = pw[l*DD + (k - HH*DD)];
        }
    }
    g_Wbig[idx] = v;
}

__global__ void p5_small(const float* __restrict__ inb, const float* __restrict__ pw,
                         const float* __restrict__ outb, const float* __restrict__ mt) {
    int tid = threadIdx.x;
    if (tid < NTP) {
        float acc = 0.f;
        if (tid < NT) {
            int sq = tid / HH, h = tid % HH;
            for (int j = 0; j < HDD; j++)
                acc += g_qconst[sq*DD + h*HDD + j] * inb[DD + h*HDD + j];
        }
        g_c0[tid] = acc;
    }
    if (tid < NL) {
        int l = tid;
        float a = 0.f, b = 0.f, c = 0.f;
        if (l < LL) {
            for (int d = 0; d < DD; d++) {
                a += g_M[l*DD + d] * inb[2*DD + d];
                b += pw[l*DD + d] * outb[d];
                float ms = 0.f;
                for (int s = 0; s < SS; s++) ms += mt[s*DD + d];
                c += pw[l*DD + d] * ms;
            }
        }
        g_bvM[l] = a; g_boutP[l] = b; g_msumP[l] = c;
    }
}

// ---------------- K1: scores GEMM  C[47104][192] = cls @ sproj^T + c0 ----------------
__global__ void __launch_bounds__(256) k1_scores(const float* __restrict__ A) {
    __shared__ float As[2][8][132];
    __shared__ float Bs[2][8][68];
    int tid = threadIdx.x;
    int m0 = blockIdx.x * 128;
    int n0 = blockIdx.y * 64;
    int ty = tid >> 4, tx = tid & 15;
    int arow = tid >> 1, acol = (tid & 1) * 4;
    int brow = tid >> 2, bcol = (tid & 3) * 2;

    const float* aptr = A + (size_t)(m0 + arow)*DD + acol;
    const float* bptr = g_sproj + (size_t)(n0 + brow)*DD + bcol;

    {
        float4 av = *(const float4*)aptr;
        As[0][acol+0][arow] = av.x; As[0][acol+1][arow] = av.y;
        As[0][acol+2][arow] = av.z; As[0][acol+3][arow] = av.w;
        float2 bv = *(const float2*)bptr;
        Bs[0][bcol+0][brow] = bv.x; Bs[0][bcol+1][brow] = bv.y;
    }
    __syncthreads();

    float acc[8][4];
    #pragma unroll
    for (int i = 0; i < 8; i++)
        #pragma unroll
        for (int j = 0; j < 4; j++) acc[i][j] = 0.f;

    const int NK = DD / 8;
    for (int kt = 0; kt < NK; kt++) {
        int cur = kt & 1, nxt = cur ^ 1;
        float4 av; float2 bv;
        bool more = (kt + 1 < NK);
        if (more) {
            av = *(const float4*)(aptr + (kt+1)*8);
            bv = *(const float2*)(bptr + (kt+1)*8);
        }
        #pragma unroll
        for (int kk = 0; kk < 8; kk++) {
            float4 a0 = *(const float4*)&As[cur][kk][ty*8];
            float4 a1 = *(const float4*)&As[cur][kk][ty*8 + 4];
            float4 b0 = *(const float4*)&Bs[cur][kk][tx*4];
            float a[8] = {a0.x,a0.y,a0.z,a0.w,a1.x,a1.y,a1.z,a1.w};
            float b[4] = {b0.x,b0.y,b0.z,b0.w};
            #pragma unroll
            for (int i = 0; i < 8; i++)
                #pragma unroll
                for (int j = 0; j < 4; j++) acc[i][j] += a[i]*b[j];
        }
        if (more) {
            As[nxt][acol+0][arow] = av.x; As[nxt][acol+1][arow] = av.y;
            As[nxt][acol+2][arow] = av.z; As[nxt][acol+3][arow] = av.w;
            Bs[nxt][bcol+0][brow] = bv.x; Bs[nxt][bcol+1][brow] = bv.y;
            __syncthreads();
        }
    }

    #pragma unroll
    for (int i = 0; i < 8; i++) {
        int m = m0 + ty*8 + i;
        #pragma unroll
        for (int j = 0; j < 4; j++) {
            int n = n0 + tx*4 + j;
            g_scores[(size_t)m*NTP + n] = acc[i][j] + g_c0[n];
        }
    }
}

// ---------------- K2: per-batch softmax + u + cls_sum ----------------
__global__ void __launch_bounds__(256) k2_attn(const float* __restrict__ cls,
                                               const int* __restrict__ mask) {
    __shared__ float sc[SS][NTP];
    __shared__ float mx[NT], den[NT];
    __shared__ float wsm[HH*SS];
    __shared__ int e[SS];
    __shared__ int nex;
    int b = blockIdx.x;
    int tid = threadIdx.x;

    if (tid == 0) nex = 0;
    __syncthreads();
    if (tid < SS) {
        e[tid] = mask[b*SS + tid];
        if (e[tid]) atomicAdd(&nex, 1);
    }
    for (int idx = tid; idx < SS*NTP; idx += 256)
        sc[idx / NTP][idx % NTP] = g_scores[(size_t)b*SS*NTP + idx];
    __syncthreads();

    if (tid < NT) {
        int sq = tid / HH;
        float m = -INFINITY, d = 0.f;
        if (nex > 0 && e[sq] == 0) {
            for (int sk = 0; sk < SS; sk++)
                if (e[sk]) m = fmaxf(m, sc[sk][tid]);
            for (int sk = 0; sk < SS; sk++)
                if (e[sk]) d += __expf(sc[sk][tid] - m);
        }
        mx[tid] = m; den[tid] = d;
    }
    __syncthreads();

    if (tid < HH*SS) {
        int h = tid / SS, sk = tid % SS;
        float w = 0.f;
        if (nex > 0 && e[sk]) {
            for (int sq = 0; sq < SS; sq++) {
                if (e[sq] == 0) {
                    int t = sq*HH + h;
                    w += __expf(sc[sk][t] - mx[t]) / den[t];
                }
            }
        }
        wsm[tid] = w;
    }
    __syncthreads();

    float* arow = g_A + (size_t)b * KA;
    for (int d0 = tid; d0 < DD; d0 += 256) {
        float u[HH];
        #pragma unroll
        for (int h = 0; h < HH; h++) u[h] = 0.f;
        float csum = 0.f;
        for (int sk = 0; sk < SS; sk++) {
            float c = cls[((size_t)b*SS + sk)*DD + d0];
            if (e[sk]) {
                csum += c;
                #pragma unroll
                for (int h = 0; h < HH; h++) u[h] += wsm[h*SS + sk] * c;
            }
        }
        #pragma unroll
        for (int h = 0; h < HH; h++) arow[h*DD + d0] = u[h];
        arow[HH*DD + d0] = csum;
    }
}

// ---------------- K3a: split-K logits GEMM  P[s] = A[:,k0:k0+768] @ Wbig[k0:k0+768] ----------------
__global__ void __launch_bounds__(256) k3_gemm() {
    __shared__ float As[2][8][132];
    __shared__ float Bs[2][8][68];
    int tid = threadIdx.x;
    int m0 = blockIdx.x * 128;
    int split = blockIdx.y;
    int k0 = split * 768;
    int ty = tid >> 4, tx = tid & 15;
    int arow = tid >> 1, acol = (tid & 1) * 4;
    int bk = tid >> 5, bn = (tid & 31) * 2;

    const float* aptr = g_A + (size_t)(m0 + arow)*KA + k0 + acol;
    const float* bptr = g_Wbig + (size_t)(k0 + bk)*NL + bn;

    {
        float4 av = *(const float4*)aptr;
        As[0][acol+0][arow] = av.x; As[0][acol+1][arow] = av.y;
        As[0][acol+2][arow] = av.z; As[0][acol+3][arow] = av.w;
        float2 bv = *(const float2*)bptr;
        Bs[0][bk][bn+0] = bv.x; Bs[0][bk][bn+1] = bv.y;
    }
    __syncthreads();

    float acc[8][4];
    #pragma unroll
    for (int i = 0; i < 8; i++)
        #pragma unroll
        for (int j = 0; j < 4; j++) acc[i][j] = 0.f;

    const int NK = 768 / 8;
    for (int kt = 0; kt < NK; kt++) {
        int cur = kt & 1, nxt = cur ^ 1;
        float4 av; float2 bv;
        bool more = (kt + 1 < NK);
        if (more) {
            av = *(const float4*)(aptr + (kt+1)*8);
            bv = *(const float2*)(bptr + (size_t)(kt+1)*8*NL);
        }
        #pragma unroll
        for (int kk = 0; kk < 8; kk++) {
            float4 a0 = *(const float4*)&As[cur][kk][ty*8];
            float4 a1 = *(const float4*)&As[cur][kk][ty*8 + 4];
            float4 b0 = *(const float4*)&Bs[cur][kk][tx*4];
            float a[8] = {a0.x,a0.y,a0.z,a0.w,a1.x,a1.y,a1.z,a1.w};
            float b[4] = {b0.x,b0.y,b0.z,b0.w};
            #pragma unroll
            for (int i = 0; i < 8; i++)
                #pragma unroll
                for (int j = 0; j < 4; j++) acc[i][j] += a[i]*b[j];
        }
        if (more) {
            As[nxt][acol+0][arow] = av.x; As[nxt][acol+1][arow] = av.y;
            As[nxt][acol+2][arow] = av.z; As[nxt][acol+3][arow] = av.w;
            Bs[nxt][bk][bn+0] = bv.x; Bs[nxt][bk][bn+1] = bv.y;
            __syncthreads();
        }
    }

    #pragma unroll
    for (int i = 0; i < 8; i++) {
        int m = m0 + ty*8 + i;
        #pragma unroll
        for (int j = 0; j < 4; j++) {
            int n = tx*4 + j;
            g_P[((size_t)split*BB + m)*NL + n] = acc[i][j];
        }
    }
}

// ---------------- K3b: reduce splits + scalar terms + degenerate path ----------------
__global__ void k3b_final(const int* __restrict__ mask, const float* __restrict__ pb,
                          float* __restrict__ out) {
    int idx = blockIdx.x*256 + threadIdx.x;
    if (idx >= BB*NL) return;
    int b = idx / NL, l = idx % NL;
    if (l >= LL) return;
    int nex = 0;
    for (int s = 0; s < SS; s++) nex += (mask[b*SS + s] != 0);
    float r;
    if (nex > 0) {
        float acc = 0.f;
        for (int s = 0; s < NSPLIT; s++)
            acc += g_P[((size_t)s*BB + b)*NL + l];
        float nmiss = (float)(SS - nex);
        r = (acc + nmiss*(g_bvM[l] + g_boutP[l])) * (1.f/SS) + pb[l];
    } else {
        r = g_msumP[l] * (1.f/SS) + pb[l];
    }
    out[b*LL + l] = r;
}

// ---------------- launcher ----------------
extern "C" void kernel_launch(void* const* d_in, const int* in_sizes, int n_in,
                              void* d_out, int out_size) {
    const float* cls  = (const float*)d_in[0];
    const int*   mask = (const int*)  d_in[1];
    const float* mt   = (const float*)d_in[2];
    const float* ipw  = (const float*)d_in[3];
    const float* ipb  = (const float*)d_in[4];
    const float* opw  = (const float*)d_in[5];
    const float* opb  = (const float*)d_in[6];
    const float* pw   = (const float*)d_in[7];
    const float* pb   = (const float*)d_in[8];
    float* out = (float*)d_out;

    p1_qconst<<<(SS*DD + 255)/256, 256>>>(mt, ipw, ipb);
    p2_sproj<<<(NTP*DD + 255)/256, 256>>>(ipw);
    p3_M<<<(LL*DD + 255)/256, 256>>>(pw, opw);
    p4_wbig<<<(KA*NL + 255)/256, 256>>>(ipw, pw);
    p5_small<<<1, 256>>>(ipb, pw, opb, mt);

    dim3 g1(368, 3);
    k1_scores<<<g1, 256>>>(cls);
    k2_attn<<<BB, 256>>>(cls, mask);
    dim3 g3(16, NSPLIT);
    k3_gemm<<<g3, 256>>>();
    k3b_final<<<(BB*NL + 255)/256, 256>>>(mask, pb, out);
}

// round 3
// speedup vs baseline: 1.2478x; 1.2478x over previous
#include <cuda_runtime.h>
#include <math.h>
#include <cstdint>

#define BB 2048
#define SS 23
#define DD 768
#define HH 8
#define HDD 96
#define LL 50
#define NT 184      // SS*HH (query,head) pairs
#define NTP 192     // padded to multiple of 64
#define KA 6912     // 9*768 = HH*DD + DD (u concat cls_sum)
#define NL 64       // padded logits
#define NSPLIT 9

// ---------------- scratch (static device globals; no allocation) ----------------
__device__ float g_qconst[SS*DD];          // q at missing positions (batch-constant)
__device__ float g_sproj[NTP*DD];          // Wk_h^T q_const, padded rows zeroed
__device__ float g_c0[NTP];                // q_const . bk
__device__ float g_Mt[DD*NL];              // (pred_w @ out_proj_w) transposed: [d][l]
__device__ float g_Wbig[KA*NL];            // [F | pred_w] as [K][N]
__device__ float g_bvM[NL];                // M . bv
__device__ float g_boutP[NL];              // pred_w . out_proj_b
__device__ float g_msumP[NL];              // (sum_s missing_table) . pred_w
__device__ float g_scores[(size_t)BB*SS*NTP]; // raw scores, 36 MB
__device__ float g_A[(size_t)BB*KA];       // [u(6144) | cls_sum(768)] per batch
__device__ float g_P[(size_t)NSPLIT*BB*NL];// split-K partials

// ---------------- mma.sync tf32 helpers (portable sm_80+ PTX) ----------------
__device__ __forceinline__ uint32_t f2tf32(float x) {
    uint32_t r;
    asm("cvt.rna.tf32.f32 %0, %1;" : "=r"(r) : "f"(x));
    return r;
}
__device__ __forceinline__ void mma_tf32(float* d,
                                         uint32_t a0, uint32_t a1, uint32_t a2, uint32_t a3,
                                         uint32_t b0, uint32_t b1) {
    asm volatile(
        "mma.sync.aligned.m16n8k8.row.col.f32.tf32.tf32.f32 "
        "{%0,%1,%2,%3}, {%4,%5,%6,%7}, {%8,%9}, {%0,%1,%2,%3};"
        : "+f"(d[0]), "+f"(d[1]), "+f"(d[2]), "+f"(d[3])
        : "r"(a0), "r"(a1), "r"(a2), "r"(a3), "r"(b0), "r"(b1));
}

// ---------------- precompute kernels ----------------
__global__ void p1_qconst(const float* __restrict__ mt, const float* __restrict__ W,
                          const float* __restrict__ bias) {
    int idx = blockIdx.x*256 + threadIdx.x;
    if (idx >= SS*DD) return;
    int sq = idx / DD, c = idx % DD;
    const float* m = mt + sq*DD;
    const float* w = W + (size_t)c*DD;
    float acc = bias[c];
    for (int k = 0; k < DD; k++) acc += m[k]*w[k];
    g_qconst[idx] = acc * rsqrtf((float)HDD);
}

__global__ void p2_sproj(const float* __restrict__ W) {
    int idx = blockIdx.x*256 + threadIdx.x;
    if (idx >= NTP*DD) return;
    int t = idx / DD, d = idx % DD;
    if (t >= NT) { g_sproj[idx] = 0.f; return; }
    int sq = t / HH, h = t % HH;
    const float* q = g_qconst + sq*DD + h*HDD;
    float acc = 0.f;
    for (int j = 0; j < HDD; j++)
        acc += q[j] * W[(size_t)(DD + h*HDD + j)*DD + d];
    g_sproj[idx] = acc;
}

// Mt[d][l] = sum_j pred_w[l][j] * out_proj_w[j][d]   (transposed storage)
__global__ void p3_Mt(const float* __restrict__ pw, const float* __restrict__ ow) {
    int idx = blockIdx.x*256 + threadIdx.x;
    if (idx >= DD*NL) return;
    int l = idx & 63;
    int d = idx >> 6;
    float acc = 0.f;
    if (l < LL) {
        const float* pr = pw + l*DD;
        for (int j = 0; j < DD; j++)
            acc += pr[j] * ow[(size_t)j*DD + d];
    }
    g_Mt[idx] = acc;
}

__global__ void p4_wbig(const float* __restrict__ W, const float* __restrict__ pw) {
    int idx = blockIdx.x*256 + threadIdx.x;
    if (idx >= KA*NL) return;
    int l = idx & 63;          // fastest -> coalesced g_Mt reads
    int k = idx >> 6;
    float v = 0.f;
    if (l < LL) {
        if (k < HH*DD) {
            int h = k / DD, d = k % DD;
            float acc = 0.f;
            for (int t = 0; t < HDD; t++)
                acc += g_Mt[(h*HDD + t)*NL + l] * W[(size_t)(2*DD + h*HDD + t)*DD + d];
            v = acc;
        } else {
            v = pw[l*DD + (k - HH*DD)];
        }
    }
    g_Wbig[idx] = v;   // [k][l], coalesced
}

__global__ void p5_small(const float* __restrict__ inb, const float* __restrict__ pw,
                         const float* __restrict__ outb, const float* __restrict__ mt) {
    int tid = threadIdx.x;
    if (tid < NTP) {
        float acc = 0.f;
        if (tid < NT) {
            int sq = tid / HH, h = tid % HH;
            for (int j = 0; j < HDD; j++)
                acc += g_qconst[sq*DD + h*HDD + j] * inb[DD + h*HDD + j];
        }
        g_c0[tid] = acc;
    }
    if (tid < NL) {
        int l = tid;
        float a = 0.f, b = 0.f, c = 0.f;
        if (l < LL) {
            for (int d = 0; d < DD; d++) {
                a += g_Mt[d*NL + l] * inb[2*DD + d];
                b += pw[l*DD + d] * outb[d];
                float ms = 0.f;
                for (int s = 0; s < SS; s++) ms += mt[s*DD + d];
                c += pw[l*DD + d] * ms;
            }
        }
        g_bvM[l] = a; g_boutP[l] = b; g_msumP[l] = c;
    }
}

// ---------------- K1: scores GEMM via mma.sync tf32 ----------------
// C[47104][192] = cls[47104][768] @ sproj[192][768]^T + c0
// CTA: 128M x 96N, grid (368, 2). 8 warps in 4x2; warp = 32M x 48N.
// K in 32-wide double-buffered smem chunks, tf32-converted on the fly.
#define K1_STRIDE 36
#define K1_AS_WORDS (2*128*K1_STRIDE)           // 9216
#define K1_BS_WORDS (2*96*K1_STRIDE)            // 6912
#define K1_SMEM ((K1_AS_WORDS + K1_BS_WORDS)*4) // 64512 bytes
#define K1_NCHUNK 24

__global__ void __launch_bounds__(256, 2) k1_mma(const float* __restrict__ A) {
    extern __shared__ uint32_t sm[];
    uint32_t* AsU = sm;                 // [2][128][36]
    uint32_t* BsU = sm + K1_AS_WORDS;   // [2][96][36]

    int tid = threadIdx.x;
    int wid = tid >> 5;
    int lane = tid & 31;
    int g = lane >> 2, t = lane & 3;
    int m0 = blockIdx.x * 128;
    int n0 = blockIdx.y * 96;
    int wm = (wid & 3) * 32;
    int wn = (wid >> 2) * 48;

    // loader indices
    int ar = tid >> 1, aq = (tid & 1) * 4;      // not used; use f-pattern instead

    // ---- preload chunk 0 into buffer 0 ----
    {
        #pragma unroll
        for (int p = 0; p < 4; p++) {   // A: 128 rows x 8 float4
            int f = p*256 + tid; int r = f >> 3, q = f & 7;
            float4 v = *(const float4*)(A + (size_t)(m0 + r)*DD + q*4);
            uint32_t* d = AsU + r*K1_STRIDE + q*4;
            d[0] = f2tf32(v.x); d[1] = f2tf32(v.y); d[2] = f2tf32(v.z); d[3] = f2tf32(v.w);
        }
        #pragma unroll
        for (int p = 0; p < 3; p++) {   // B: 96 rows x 8 float4
            int f = p*256 + tid; int r = f >> 3, q = f & 7;
            float4 v = *(const float4*)(g_sproj + (size_t)(n0 + r)*DD + q*4);
            uint32_t* d = BsU + r*K1_STRIDE + q*4;
            d[0] = f2tf32(v.x); d[1] = f2tf32(v.y); d[2] = f2tf32(v.z); d[3] = f2tf32(v.w);
        }
    }
    __syncthreads();

    float acc[2][6][4];
    #pragma unroll
    for (int i = 0; i < 2; i++)
        #pragma unroll
        for (int j = 0; j < 6; j++)
            #pragma unroll
            for (int q = 0; q < 4; q++) acc[i][j][q] = 0.f;

    for (int c = 0; c < K1_NCHUNK; c++) {
        int cb = c & 1;
        bool more = (c + 1 < K1_NCHUNK);
        float4 ra[4], rb[3];
        if (more) {
            int kc = (c + 1) * 32;
            #pragma unroll
            for (int p = 0; p < 4; p++) {
                int f = p*256 + tid; int r = f >> 3, q = f & 7;
                ra[p] = *(const float4*)(A + (size_t)(m0 + r)*DD + kc + q*4);
            }
            #pragma unroll
            for (int p = 0; p < 3; p++) {
                int f = p*256 + tid; int r = f >> 3, q = f & 7;
                rb[p] = *(const float4*)(g_sproj + (size_t)(n0 + r)*DD + kc + q*4);
            }
        }

        const uint32_t* As_ = AsU + cb*128*K1_STRIDE;
        const uint32_t* Bs_ = BsU + cb*96*K1_STRIDE;
        #pragma unroll
        for (int ks = 0; ks < 4; ks++) {
            int k0 = ks*8;
            uint32_t afr[2][4];
            #pragma unroll
            for (int mt = 0; mt < 2; mt++) {
                const uint32_t* r0 = As_ + (wm + mt*16 + g)*K1_STRIDE + k0;
                afr[mt][0] = r0[t];
                afr[mt][1] = r0[8*K1_STRIDE + t];
                afr[mt][2] = r0[t + 4];
                afr[mt][3] = r0[8*K1_STRIDE + t + 4];
            }
            #pragma unroll
            for (int nt = 0; nt < 6; nt++) {
                const uint32_t* rB = Bs_ + (wn + nt*8 + g)*K1_STRIDE + k0;
                uint32_t b0 = rB[t], b1 = rB[t + 4];
                mma_tf32(acc[0][nt], afr[0][0], afr[0][1], afr[0][2], afr[0][3], b0, b1);
                mma_tf32(acc[1][nt], afr[1][0], afr[1][1], afr[1][2], afr[1][3], b0, b1);
            }
        }

        if (more) {
            int nb = (c + 1) & 1;
            uint32_t* Ad = AsU + nb*128*K1_STRIDE;
            uint32_t* Bd = BsU + nb*96*K1_STRIDE;
            #pragma unroll
            for (int p = 0; p < 4; p++) {
                int f = p*256 + tid; int r = f >> 3, q = f & 7;
                uint32_t* d = Ad + r*K1_STRIDE + q*4;
                d[0] = f2tf32(ra[p].x); d[1] = f2tf32(ra[p].y);
                d[2] = f2tf32(ra[p].z); d[3] = f2tf32(ra[p].w);
            }
            #pragma unroll
            for (int p = 0; p < 3; p++) {
                int f = p*256 + tid; int r = f >> 3, q = f & 7;
                uint32_t* d = Bd + r*K1_STRIDE + q*4;
                d[0] = f2tf32(rb[p].x); d[1] = f2tf32(rb[p].y);
                d[2] = f2tf32(rb[p].z); d[3] = f2tf32(rb[p].w);
            }
            __syncthreads();
        }
    }

    // epilogue: D layout per mma: c0,c1 at row g cols 2t,2t+1; c2,c3 at row g+8
    #pragma unroll
    for (int mt = 0; mt < 2; mt++) {
        int m = m0 + wm + mt*16 + g;
        float* row0 = g_scores + (size_t)m * NTP;
        float* row1 = row0 + 8*NTP;
        #pragma unroll
        for (int nt = 0; nt < 6; nt++) {
            int n = n0 + wn + nt*8 + 2*t;
            float c00 = g_c0[n], c01 = g_c0[n+1];
            float2 v0 = make_float2(acc[mt][nt][0] + c00, acc[mt][nt][1] + c01);
            float2 v1 = make_float2(acc[mt][nt][2] + c00, acc[mt][nt][3] + c01);
            *(float2*)(row0 + n) = v0;
            *(float2*)(row1 + n) = v1;
        }
    }
}

// ---------------- K2: per-batch softmax + u + cls_sum ----------------
__global__ void __launch_bounds__(256) k2_attn(const float* __restrict__ cls,
                                               const int* __restrict__ mask) {
    __shared__ float sc[SS][NTP];
    __shared__ float mx[NT], den[NT];
    __shared__ float wsm[HH*SS];
    __shared__ int e[SS];
    __shared__ int nex;
    int b = blockIdx.x;
    int tid = threadIdx.x;

    if (tid == 0) nex = 0;
    __syncthreads();
    if (tid < SS) {
        e[tid] = mask[b*SS + tid];
        if (e[tid]) atomicAdd(&nex, 1);
    }
    for (int idx = tid; idx < SS*NTP; idx += 256)
        sc[idx / NTP][idx % NTP] = g_scores[(size_t)b*SS*NTP + idx];
    __syncthreads();

    if (tid < NT) {
        int sq = tid / HH;
        float m = -INFINITY, d = 0.f;
        if (nex > 0 && e[sq] == 0) {
            for (int sk = 0; sk < SS; sk++)
                if (e[sk]) m = fmaxf(m, sc[sk][tid]);
            for (int sk = 0; sk < SS; sk++)
                if (e[sk]) d += __expf(sc[sk][tid] - m);
        }
        mx[tid] = m; den[tid] = d;
    }
    __syncthreads();

    if (tid < HH*SS) {
        int h = tid / SS, sk = tid % SS;
        float w = 0.f;
        if (nex > 0 && e[sk]) {
            for (int sq = 0; sq < SS; sq++) {
                if (e[sq] == 0) {
                    int t = sq*HH + h;
                    w += __expf(sc[sk][t] - mx[t]) / den[t];
                }
            }
        }
        wsm[tid] = w;
    }
    __syncthreads();

    float* arow = g_A + (size_t)b * KA;
    for (int d0 = tid; d0 < DD; d0 += 256) {
        float u[HH];
        #pragma unroll
        for (int h = 0; h < HH; h++) u[h] = 0.f;
        float csum = 0.f;
        for (int sk = 0; sk < SS; sk++) {
            float c = cls[((size_t)b*SS + sk)*DD + d0];
            if (e[sk]) {
                csum += c;
                #pragma unroll
                for (int h = 0; h < HH; h++) u[h] += wsm[h*SS + sk] * c;
            }
        }
        #pragma unroll
        for (int h = 0; h < HH; h++) arow[h*DD + d0] = u[h];
        arow[HH*DD + d0] = csum;
    }
}

// ---------------- K3a: split-K logits GEMM ----------------
__global__ void __launch_bounds__(256) k3_gemm() {
    __shared__ float As[2][8][132];
    __shared__ float Bs[2][8][68];
    int tid = threadIdx.x;
    int m0 = blockIdx.x * 128;
    int split = blockIdx.y;
    int k0 = split * 768;
    int ty = tid >> 4, tx = tid & 15;
    int arow = tid >> 1, acol = (tid & 1) * 4;
    int bk = tid >> 5, bn = (tid & 31) * 2;

    const float* aptr = g_A + (size_t)(m0 + arow)*KA + k0 + acol;
    const float* bptr = g_Wbig + (size_t)(k0 + bk)*NL + bn;

    {
        float4 av = *(const float4*)aptr;
        As[0][acol+0][arow] = av.x; As[0][acol+1][arow] = av.y;
        As[0][acol+2][arow] = av.z; As[0][acol+3][arow] = av.w;
        float2 bv = *(const float2*)bptr;
        Bs[0][bk][bn+0] = bv.x; Bs[0][bk][bn+1] = bv.y;
    }
    __syncthreads();

    float acc[8][4];
    #pragma unroll
    for (int i = 0; i < 8; i++)
        #pragma unroll
        for (int j = 0; j < 4; j++) acc[i][j] = 0.f;

    const int NK = 768 / 8;
    for (int kt = 0; kt < NK; kt++) {
        int cur = kt & 1, nxt = cur ^ 1;
        float4 av; float2 bv;
        bool more = (kt + 1 < NK);
        if (more) {
            av = *(const float4*)(aptr + (kt+1)*8);
            bv = *(const float2*)(bptr + (size_t)(kt+1)*8*NL);
        }
        #pragma unroll
        for (int kk = 0; kk < 8; kk++) {
            float4 a0 = *(const float4*)&As[cur][kk][ty*8];
            float4 a1 = *(const float4*)&As[cur][kk][ty*8 + 4];
            float4 b0 = *(const float4*)&Bs[cur][kk][tx*4];
            float a[8] = {a0.x,a0.y,a0.z,a0.w,a1.x,a1.y,a1.z,a1.w};
            float b[4] = {b0.x,b0.y,b0.z,b0.w};
            #pragma unroll
            for (int i = 0; i < 8; i++)
                #pragma unroll
                for (int j = 0; j < 4; j++) acc[i][j] += a[i]*b[j];
        }
        if (more) {
            As[nxt][acol+0][arow] = av.x; As[nxt][acol+1][arow] = av.y;
            As[nxt][acol+2][arow] = av.z; As[nxt][acol+3][arow] = av.w;
            Bs[nxt][bk][bn+0] = bv.x; Bs[nxt][bk][bn+1] = bv.y;
            __syncthreads();
        }
    }

    #pragma unroll
    for (int i = 0; i < 8; i++) {
        int m = m0 + ty*8 + i;
        #pragma unroll
        for (int j = 0; j < 4; j++) {
            int n = tx*4 + j;
            g_P[((size_t)split*BB + m)*NL + n] = acc[i][j];
        }
    }
}

// ---------------- K3b: reduce splits + scalar terms + degenerate path ----------------
__global__ void k3b_final(const int* __restrict__ mask, const float* __restrict__ pb,
                          float* __restrict__ out) {
    int idx = blockIdx.x*256 + threadIdx.x;
    if (idx >= BB*NL) return;
    int b = idx / NL, l = idx % NL;
    if (l >= LL) return;
    int nex = 0;
    for (int s = 0; s < SS; s++) nex += (mask[b*SS + s] != 0);
    float r;
    if (nex > 0) {
        float acc = 0.f;
        for (int s = 0; s < NSPLIT; s++)
            acc += g_P[((size_t)s*BB + b)*NL + l];
        float nmiss = (float)(SS - nex);
        r = (acc + nmiss*(g_bvM[l] + g_boutP[l])) * (1.f/SS) + pb[l];
    } else {
        r = g_msumP[l] * (1.f/SS) + pb[l];
    }
    out[b*LL + l] = r;
}

// ---------------- launcher ----------------
extern "C" void kernel_launch(void* const* d_in, const int* in_sizes, int n_in,
                              void* d_out, int out_size) {
    const float* cls  = (const float*)d_in[0];
    const int*   mask = (const int*)  d_in[1];
    const float* mt   = (const float*)d_in[2];
    const float* ipw  = (const float*)d_in[3];
    const float* ipb  = (const float*)d_in[4];
    const float* opw  = (const float*)d_in[5];
    const float* opb  = (const float*)d_in[6];
    const float* pw   = (const float*)d_in[7];
    const float* pb   = (const float*)d_in[8];
    float* out = (float*)d_out;

    cudaFuncSetAttribute(k1_mma, cudaFuncAttributeMaxDynamicSharedMemorySize, K1_SMEM);

    p1_qconst<<<(SS*DD + 255)/256, 256>>>(mt, ipw, ipb);
    p2_sproj<<<(NTP*DD + 255)/256, 256>>>(ipw);
    p3_Mt<<<(DD*NL + 255)/256, 256>>>(pw, opw);
    p4_wbig<<<(KA*NL + 255)/256, 256>>>(ipw, pw);
    p5_small<<<1, 256>>>(ipb, pw, opb, mt);

    dim3 g1(368, 2);
    k1_mma<<<g1, 256, K1_SMEM>>>(cls);
    k2_attn<<<BB, 256>>>(cls, mask);
    dim3 g3(16, NSPLIT);
    k3_gemm<<<g3, 256>>>();
    k3b_final<<<(BB*NL + 255)/256, 256>>>(mask, pb, out);
}

// round 4
// speedup vs baseline: 1.7342x; 1.3898x over previous
#include <cuda_runtime.h>
#include <cuda_bf16.h>
#include <math.h>
#include <cstdint>

#define BB 2048
#define SS 23
#define DD 768
#define HH 8
#define HDD 96
#define LL 50
#define NT 184      // SS*HH (query,head) pairs
#define NTP 192     // padded to multiple of 64
#define KA 6912     // 9*768 = HH*DD + DD (u concat cls_sum)
#define NL 64       // padded logits
#define NSPLIT 9

// ---------------- scratch (static device globals; no allocation) ----------------
__device__ float g_qconst[SS*DD];
__device__ float g_sproj[NTP*DD];
__device__ float g_c0[NTP];
__device__ float g_Mt[DD*NL];
__device__ float g_Wbig[KA*NL];
__device__ float g_bvM[NL];
__device__ float g_boutP[NL];
__device__ float g_msumP[NL];
__device__ float g_scores[(size_t)BB*SS*NTP];
__device__ float g_A[(size_t)BB*KA];
__device__ float g_P[(size_t)NSPLIT*BB*NL];

// ---------------- mma/ldmatrix helpers (portable sm_80+ PTX) ----------------
__device__ __forceinline__ uint32_t smem_u32(const void* p) {
    uint32_t a;
    asm("{ .reg .u64 t; cvta.to.shared.u64 t, %1; cvt.u32.u64 %0, t; }" : "=r"(a) : "l"(p));
    return a;
}
__device__ __forceinline__ void ldsm_x4(uint32_t& r0, uint32_t& r1, uint32_t& r2, uint32_t& r3,
                                        uint32_t addr) {
    asm volatile("ldmatrix.sync.aligned.m8n8.x4.shared.b16 {%0,%1,%2,%3}, [%4];"
                 : "=r"(r0), "=r"(r1), "=r"(r2), "=r"(r3) : "r"(addr));
}
__device__ __forceinline__ void mma_bf16(float* d,
                                         uint32_t a0, uint32_t a1, uint32_t a2, uint32_t a3,
                                         uint32_t b0, uint32_t b1) {
    asm volatile(
        "mma.sync.aligned.m16n8k16.row.col.f32.bf16.bf16.f32 "
        "{%0,%1,%2,%3}, {%4,%5,%6,%7}, {%8,%9}, {%0,%1,%2,%3};"
        : "+f"(d[0]), "+f"(d[1]), "+f"(d[2]), "+f"(d[3])
        : "r"(a0), "r"(a1), "r"(a2), "r"(a3), "r"(b0), "r"(b1));
}
__device__ __forceinline__ uint32_t pack_bf16(float lo, float hi) {
    __nv_bfloat162 v = __floats2bfloat162_rn(lo, hi);
    return *reinterpret_cast<uint32_t*>(&v);
}

// ---------------- precompute kernels ----------------
__global__ void p1_qconst(const float* __restrict__ mt, const float* __restrict__ W,
                          const float* __restrict__ bias) {
    int idx = blockIdx.x*256 + threadIdx.x;
    if (idx >= SS*DD) return;
    int sq = idx / DD, c = idx % DD;
    const float* m = mt + sq*DD;
    const float* w = W + (size_t)c*DD;
    float acc = bias[c];
    for (int k = 0; k < DD; k++) acc += m[k]*w[k];
    g_qconst[idx] = acc * rsqrtf((float)HDD);
}

__global__ void p2_sproj(const float* __restrict__ W) {
    int idx = blockIdx.x*256 + threadIdx.x;
    if (idx >= NTP*DD) return;
    int t = idx / DD, d = idx % DD;
    if (t >= NT) { g_sproj[idx] = 0.f; return; }
    int sq = t / HH, h = t % HH;
    const float* q = g_qconst + sq*DD + h*HDD;
    float acc = 0.f;
    for (int j = 0; j < HDD; j++)
        acc += q[j] * W[(size_t)(DD + h*HDD + j)*DD + d];
    g_sproj[idx] = acc;
}

__global__ void p3_Mt(const float* __restrict__ pw, const float* __restrict__ ow) {
    int idx = blockIdx.x*256 + threadIdx.x;
    if (idx >= DD*NL) return;
    int l = idx & 63;
    int d = idx >> 6;
    float acc = 0.f;
    if (l < LL) {
        const float* pr = pw + l*DD;
        for (int j = 0; j < DD; j++)
            acc += pr[j] * ow[(size_t)j*DD + d];
    }
    g_Mt[idx] = acc;
}

__global__ void p4_wbig(const float* __restrict__ W, const float* __restrict__ pw) {
    int idx = blockIdx.x*256 + threadIdx.x;
    if (idx >= KA*NL) return;
    int l = idx & 63;
    int k = idx >> 6;
    float v = 0.f;
    if (l < LL) {
        if (k < HH*DD) {
            int h = k / DD, d = k % DD;
            float acc = 0.f;
            for (int t = 0; t < HDD; t++)
                acc += g_Mt[(h*HDD + t)*NL + l] * W[(size_t)(2*DD + h*HDD + t)*DD + d];
            v = acc;
        } else {
            v = pw[l*DD + (k - HH*DD)];
        }
    }
    g_Wbig[idx] = v;
}

// p5a: c0[t] = q_const . bk   (192 threads, 96-length loops)
__global__ void p5a_c0(const float* __restrict__ inb) {
    int tid = threadIdx.x;
    if (tid >= NTP) return;
    float acc = 0.f;
    if (tid < NT) {
        int sq = tid / HH, h = tid % HH;
        for (int j = 0; j < HDD; j++)
            acc += g_qconst[sq*DD + h*HDD + j] * inb[DD + h*HDD + j];
    }
    g_c0[tid] = acc;
}

// p5b: per-l reductions (grid 64 blocks, block 256)
__global__ void __launch_bounds__(256) p5b_terms(const float* __restrict__ inb,
                                                 const float* __restrict__ pw,
                                                 const float* __restrict__ outb,
                                                 const float* __restrict__ mt) {
    __shared__ float ra[32], rb[32], rc[32];
    int l = blockIdx.x;
    int tid = threadIdx.x;
    float a = 0.f, b = 0.f, c = 0.f;
    if (l < LL) {
        for (int d = tid; d < DD; d += 256) {
            float m = g_Mt[d*NL + l];
            float p = pw[l*DD + d];
            float ms = 0.f;
            #pragma unroll
            for (int s = 0; s < SS; s++) ms += mt[s*DD + d];
            a += m * inb[2*DD + d];
            b += p * outb[d];
            c += p * ms;
        }
    }
    #pragma unroll
    for (int o = 16; o > 0; o >>= 1) {
        a += __shfl_down_sync(0xFFFFFFFF, a, o);
        b += __shfl_down_sync(0xFFFFFFFF, b, o);
        c += __shfl_down_sync(0xFFFFFFFF, c, o);
    }
    int w = tid >> 5, ln = tid & 31;
    if (ln == 0) { ra[w] = a; rb[w] = b; rc[w] = c; }
    __syncthreads();
    if (tid == 0) {
        float sa = 0.f, sb = 0.f, sc2 = 0.f;
        for (int i = 0; i < 8; i++) { sa += ra[i]; sb += rb[i]; sc2 += rc[i]; }
        g_bvM[l] = sa; g_boutP[l] = sb; g_msumP[l] = sc2;
    }
}

// ---------------- K1: scores GEMM via mma.sync bf16 + ldmatrix ----------------
// C[47104][192] = cls @ sproj^T + c0.  CTA 128M x 192N, 512 thr / 16 warps (4m x 4n),
// warp tile 32M x 48N.  K chunks of 32 bf16, double buffered. smem stride 40 half.
#define SKW 40
#define K1_ABUF 10240                   // 128*40*2 bytes per buffer
#define K1_BBUF 15360                   // 192*40*2 bytes per buffer
#define K1_BOFF (2*K1_ABUF)             // 20480
#define K1_SMEM (2*K1_ABUF + 2*K1_BBUF) // 51200
#define K1_NCHUNK 24

__global__ void __launch_bounds__(512, 1) k1_mma(const float* __restrict__ A) {
    extern __shared__ char smem[];
    uint32_t sb = smem_u32(smem);

    int tid = threadIdx.x;
    int wid = tid >> 5;
    int lane = tid & 31;
    int g = lane >> 2, t = lane & 3;
    int l16 = lane & 15, lhi = lane >> 4;
    int l8 = lane & 7, lm8 = (lane >> 3) & 1;

    int m0 = blockIdx.x * 128;
    int wm = (wid & 3) * 32;
    int wn = (wid >> 2) * 48;

    // loader indices: A rows 128 x 4 segs (512 segs), B rows 192 x 4 segs (768 segs)
    int arow = tid >> 2, aq = tid & 3;
    const float* agp = A + (size_t)(m0 + arow)*DD + aq*8;
    uint32_t asts = sb + (arow*SKW + aq*8)*2;
    int brow0 = tid >> 2;                 // first 512 segs
    int bq0 = tid & 3;
    int f1 = 512 + tid;                   // second 256 segs (tid<256)
    int brow1 = f1 >> 2, bq1 = f1 & 3;
    const float* bgp0 = g_sproj + (size_t)brow0*DD + bq0*8;
    const float* bgp1 = g_sproj + (size_t)brow1*DD + bq1*8;
    uint32_t bsts0 = sb + K1_BOFF + (brow0*SKW + bq0*8)*2;
    uint32_t bsts1 = sb + K1_BOFF + (brow1*SKW + bq1*8)*2;

    // fragment addresses (buffer 0, ks=0)
    uint32_t aAddr = sb + ((wm + l16)*SKW + lhi*8)*2;
    uint32_t bAddr = sb + K1_BOFF + ((wn + l8 + lhi*8)*SKW + lm8*8)*2;

    // ---- preload chunk 0 ----
    {
        float4 v0 = *(const float4*)agp;
        float4 v1 = *(const float4*)(agp + 4);
        uint4 pk;
        pk.x = pack_bf16(v0.x, v0.y); pk.y = pack_bf16(v0.z, v0.w);
        pk.z = pack_bf16(v1.x, v1.y); pk.w = pack_bf16(v1.z, v1.w);
        *(uint4*)(smem + (asts - sb)) = pk;
        float4 w0 = *(const float4*)bgp0;
        float4 w1 = *(const float4*)(bgp0 + 4);
        pk.x = pack_bf16(w0.x, w0.y); pk.y = pack_bf16(w0.z, w0.w);
        pk.z = pack_bf16(w1.x, w1.y); pk.w = pack_bf16(w1.z, w1.w);
        *(uint4*)(smem + (bsts0 - sb)) = pk;
        if (tid < 256) {
            float4 x0 = *(const float4*)bgp1;
            float4 x1 = *(const float4*)(bgp1 + 4);
            pk.x = pack_bf16(x0.x, x0.y); pk.y = pack_bf16(x0.z, x0.w);
            pk.z = pack_bf16(x1.x, x1.y); pk.w = pack_bf16(x1.z, x1.w);
            *(uint4*)(smem + (bsts1 - sb)) = pk;
        }
    }
    __syncthreads();

    float acc[2][6][4];
    #pragma unroll
    for (int i = 0; i < 2; i++)
        #pragma unroll
        for (int j = 0; j < 6; j++)
            #pragma unroll
            for (int q = 0; q < 4; q++) acc[i][j][q] = 0.f;

    for (int c = 0; c < K1_NCHUNK; c++) {
        int cb = c & 1;
        bool more = (c + 1 < K1_NCHUNK);
        float4 v0, v1, w0, w1, x0, x1;
        if (more) {
            int kc = (c + 1) * 32;
            v0 = *(const float4*)(agp + kc);
            v1 = *(const float4*)(agp + kc + 4);
            w0 = *(const float4*)(bgp0 + kc);
            w1 = *(const float4*)(bgp0 + kc + 4);
            if (tid < 256) {
                x0 = *(const float4*)(bgp1 + kc);
                x1 = *(const float4*)(bgp1 + kc + 4);
            }
        }

        uint32_t aB = aAddr + cb*K1_ABUF;
        uint32_t bB = bAddr + cb*K1_BBUF;
        #pragma unroll
        for (int ks = 0; ks < 2; ks++) {
            uint32_t af[2][4];
            ldsm_x4(af[0][0], af[0][1], af[0][2], af[0][3], aB + ks*32);
            ldsm_x4(af[1][0], af[1][1], af[1][2], af[1][3], aB + 16*SKW*2 + ks*32);
            uint32_t bf[6][2];
            #pragma unroll
            for (int np = 0; np < 3; np++)
                ldsm_x4(bf[2*np][0], bf[2*np][1], bf[2*np+1][0], bf[2*np+1][1],
                        bB + np*16*SKW*2 + ks*32);
            #pragma unroll
            for (int mt = 0; mt < 2; mt++)
                #pragma unroll
                for (int nt = 0; nt < 6; nt++)
                    mma_bf16(acc[mt][nt], af[mt][0], af[mt][1], af[mt][2], af[mt][3],
                             bf[nt][0], bf[nt][1]);
        }

        if (more) {
            int nb = (c + 1) & 1;
            uint4 pk;
            pk.x = pack_bf16(v0.x, v0.y); pk.y = pack_bf16(v0.z, v0.w);
            pk.z = pack_bf16(v1.x, v1.y); pk.w = pack_bf16(v1.z, v1.w);
            *(uint4*)(smem + (asts - sb) + nb*K1_ABUF) = pk;
            pk.x = pack_bf16(w0.x, w0.y); pk.y = pack_bf16(w0.z, w0.w);
            pk.z = pack_bf16(w1.x, w1.y); pk.w = pack_bf16(w1.z, w1.w);
            *(uint4*)(smem + (bsts0 - sb) + nb*K1_BBUF) = pk;
            if (tid < 256) {
                pk.x = pack_bf16(x0.x, x0.y); pk.y = pack_bf16(x0.z, x0.w);
                pk.z = pack_bf16(x1.x, x1.y); pk.w = pack_bf16(x1.z, x1.w);
                *(uint4*)(smem + (bsts1 - sb) + nb*K1_BBUF) = pk;
            }
            __syncthreads();
        }
    }

    // epilogue: acc[mt][nt][0..1] -> (row g, cols 2t,2t+1); [2..3] -> row g+8
    #pragma unroll
    for (int mt = 0; mt < 2; mt++) {
        int m = m0 + wm + mt*16 + g;
        float* row0 = g_scores + (size_t)m * NTP;
        float* row1 = row0 + 8*NTP;
        #pragma unroll
        for (int nt = 0; nt < 6; nt++) {
            int n = wn + nt*8 + 2*t;
            float c00 = g_c0[n], c01 = g_c0[n+1];
            *(float2*)(row0 + n) = make_float2(acc[mt][nt][0] + c00, acc[mt][nt][1] + c01);
            *(float2*)(row1 + n) = make_float2(acc[mt][nt][2] + c00, acc[mt][nt][3] + c01);
        }
    }
}

// ---------------- K2: per-batch softmax + u + cls_sum ----------------
__global__ void __launch_bounds__(256) k2_attn(const float* __restrict__ cls,
                                               const int* __restrict__ mask) {
    __shared__ float sc[SS][NTP];
    __shared__ float mx[NT], den[NT];
    __shared__ float wsm[HH*SS];
    __shared__ int e[SS];
    __shared__ int nex;
    int b = blockIdx.x;
    int tid = threadIdx.x;

    if (tid == 0) nex = 0;
    __syncthreads();
    if (tid < SS) {
        e[tid] = mask[b*SS + tid];
        if (e[tid]) atomicAdd(&nex, 1);
    }
    for (int idx = tid; idx < SS*NTP; idx += 256)
        sc[idx / NTP][idx % NTP] = g_scores[(size_t)b*SS*NTP + idx];
    __syncthreads();

    if (tid < NT) {
        int sq = tid / HH;
        float m = -INFINITY, d = 0.f;
        if (nex > 0 && e[sq] == 0) {
            for (int sk = 0; sk < SS; sk++)
                if (e[sk]) m = fmaxf(m, sc[sk][tid]);
            for (int sk = 0; sk < SS; sk++)
                if (e[sk]) d += __expf(sc[sk][tid] - m);
        }
        mx[tid] = m; den[tid] = d;
    }
    __syncthreads();

    if (tid < HH*SS) {
        int h = tid / SS, sk = tid % SS;
        float w = 0.f;
        if (nex > 0 && e[sk]) {
            for (int sq = 0; sq < SS; sq++) {
                if (e[sq] == 0) {
                    int t = sq*HH + h;
                    w += __expf(sc[sk][t] - mx[t]) / den[t];
                }
            }
        }
        wsm[tid] = w;
    }
    __syncthreads();

    float* arow = g_A + (size_t)b * KA;
    for (int d0 = tid; d0 < DD; d0 += 256) {
        float u[HH];
        #pragma unroll
        for (int h = 0; h < HH; h++) u[h] = 0.f;
        float csum = 0.f;
        for (int sk = 0; sk < SS; sk++) {
            float c = cls[((size_t)b*SS + sk)*DD + d0];
            if (e[sk]) {
                csum += c;
                #pragma unroll
                for (int h = 0; h < HH; h++) u[h] += wsm[h*SS + sk] * c;
            }
        }
        #pragma unroll
        for (int h = 0; h < HH; h++) arow[h*DD + d0] = u[h];
        arow[HH*DD + d0] = csum;
    }
}

// ---------------- K3a: split-K logits GEMM ----------------
__global__ void __launch_bounds__(256) k3_gemm() {
    __shared__ float As[2][8][132];
    __shared__ float Bs[2][8][68];
    int tid = threadIdx.x;
    int m0 = blockIdx.x * 128;
    int split = blockIdx.y;
    int k0 = split * 768;
    int ty = tid >> 4, tx = tid & 15;
    int arow = tid >> 1, acol = (tid & 1) * 4;
    int bk = tid >> 5, bn = (tid & 31) * 2;

    const float* aptr = g_A + (size_t)(m0 + arow)*KA + k0 + acol;
    const float* bptr = g_Wbig + (size_t)(k0 + bk)*NL + bn;

    {
        float4 av = *(const float4*)aptr;
        As[0][acol+0][arow] = av.x; As[0][acol+1][arow] = av.y;
        As[0][acol+2][arow] = av.z; As[0][acol+3][arow] = av.w;
        float2 bv = *(const float2*)bptr;
        Bs[0][bk][bn+0] = bv.x; Bs[0][bk][bn+1] = bv.y;
    }
    __syncthreads();

    float acc[8][4];
    #pragma unroll
    for (int i = 0; i < 8; i++)
        #pragma unroll
        for (int j = 0; j < 4; j++) acc[i][j] = 0.f;

    const int NK = 768 / 8;
    for (int kt = 0; kt < NK; kt++) {
        int cur = kt & 1, nxt = cur ^ 1;
        float4 av; float2 bv;
        bool more = (kt + 1 < NK);
        if (more) {
            av = *(const float4*)(aptr + (kt+1)*8);
            bv = *(const float2*)(bptr + (size_t)(kt+1)*8*NL);
        }
        #pragma unroll
        for (int kk = 0; kk < 8; kk++) {
            float4 a0 = *(const float4*)&As[cur][kk][ty*8];
            float4 a1 = *(const float4*)&As[cur][kk][ty*8 + 4];
            float4 b0 = *(const float4*)&Bs[cur][kk][tx*4];
            float a[8] = {a0.x,a0.y,a0.z,a0.w,a1.x,a1.y,a1.z,a1.w};
            float b[4] = {b0.x,b0.y,b0.z,b0.w};
            #pragma unroll
            for (int i = 0; i < 8; i++)
                #pragma unroll
                for (int j = 0; j < 4; j++) acc[i][j] += a[i]*b[j];
        }
        if (more) {
            As[nxt][acol+0][arow] = av.x; As[nxt][acol+1][arow] = av.y;
            As[nxt][acol+2][arow] = av.z; As[nxt][acol+3][arow] = av.w;
            Bs[nxt][bk][bn+0] = bv.x; Bs[nxt][bk][bn+1] = bv.y;
            __syncthreads();
        }
    }

    #pragma unroll
    for (int i = 0; i < 8; i++) {
        int m = m0 + ty*8 + i;
        #pragma unroll
        for (int j = 0; j < 4; j++) {
            int n = tx*4 + j;
            g_P[((size_t)split*BB + m)*NL + n] = acc[i][j];
        }
    }
}

// ---------------- K3b: reduce splits + scalar terms + degenerate path ----------------
__global__ void k3b_final(const int* __restrict__ mask, const float* __restrict__ pb,
                          float* __restrict__ out) {
    int idx = blockIdx.x*256 + threadIdx.x;
    if (idx >= BB*NL) return;
    int b = idx / NL, l = idx % NL;
    if (l >= LL) return;
    int nex = 0;
    for (int s = 0; s < SS; s++) nex += (mask[b*SS + s] != 0);
    float r;
    if (nex > 0) {
        float acc = 0.f;
        for (int s = 0; s < NSPLIT; s++)
            acc += g_P[((size_t)s*BB + b)*NL + l];
        float nmiss = (float)(SS - nex);
        r = (acc + nmiss*(g_bvM[l] + g_boutP[l])) * (1.f/SS) + pb[l];
    } else {
        r = g_msumP[l] * (1.f/SS) + pb[l];
    }
    out[b*LL + l] = r;
}

// ---------------- launcher ----------------
extern "C" void kernel_launch(void* const* d_in, const int* in_sizes, int n_in,
                              void* d_out, int out_size) {
    const float* cls  = (const float*)d_in[0];
    const int*   mask = (const int*)  d_in[1];
    const float* mt   = (const float*)d_in[2];
    const float* ipw  = (const float*)d_in[3];
    const float* ipb  = (const float*)d_in[4];
    const float* opw  = (const float*)d_in[5];
    const float* opb  = (const float*)d_in[6];
    const float* pw   = (const float*)d_in[7];
    const float* pb   = (const float*)d_in[8];
    float* out = (float*)d_out;

    cudaFuncSetAttribute(k1_mma, cudaFuncAttributeMaxDynamicSharedMemorySize, K1_SMEM);

    p1_qconst<<<(SS*DD + 255)/256, 256>>>(mt, ipw, ipb);
    p2_sproj<<<(NTP*DD + 255)/256, 256>>>(ipw);
    p3_Mt<<<(DD*NL + 255)/256, 256>>>(pw, opw);
    p4_wbig<<<(KA*NL + 255)/256, 256>>>(ipw, pw);
    p5a_c0<<<1, NTP>>>(ipb);
    p5b_terms<<<NL, 256>>>(ipb, pw, opb, mt);

    k1_mma<<<368, 512, K1_SMEM>>>(cls);
    k2_attn<<<BB, 256>>>(cls, mask);
    dim3 g3(16, NSPLIT);
    k3_gemm<<<g3, 256>>>();
    k3b_final<<<(BB*NL + 255)/256, 256>>>(mask, pb, out);
}

// round 5
// speedup vs baseline: 2.0865x; 1.2032x over previous
#include <cuda_runtime.h>
#include <cuda_bf16.h>
#include <math.h>
#include <cstdint>

#define BB 2048
#define SS 23
#define DD 768
#define HH 8
#define HDD 96
#define LL 50
#define NT 184      // SS*HH (query,head) pairs
#define NTP 192     // padded to multiple of 64
#define KA 6912     // 9*768 = HH*DD + DD (u concat cls_sum)
#define NL 64       // padded logits
#define NSPLIT 9

// ---------------- scratch (static device globals; no allocation) ----------------
__device__ float g_qconst[SS*DD];
__device__ float g_sproj[NTP*DD];
__device__ float g_c0[NTP];
__device__ float g_Mt[DD*NL];
__device__ float g_Wbig[KA*NL];
__device__ float g_bvM[NL];
__device__ float g_boutP[NL];
__device__ float g_msumP[NL];
__device__ float g_scores[(size_t)BB*SS*NTP];
__device__ float g_A[(size_t)BB*KA];
__device__ float g_P[(size_t)NSPLIT*BB*NL];

// ---------------- mma/ldmatrix helpers ----------------
__device__ __forceinline__ uint32_t smem_u32(const void* p) {
    uint32_t a;
    asm("{ .reg .u64 t; cvta.to.shared.u64 t, %1; cvt.u32.u64 %0, t; }" : "=r"(a) : "l"(p));
    return a;
}
__device__ __forceinline__ void ldsm_x4(uint32_t& r0, uint32_t& r1, uint32_t& r2, uint32_t& r3,
                                        uint32_t addr) {
    asm volatile("ldmatrix.sync.aligned.m8n8.x4.shared.b16 {%0,%1,%2,%3}, [%4];"
                 : "=r"(r0), "=r"(r1), "=r"(r2), "=r"(r3) : "r"(addr));
}
__device__ __forceinline__ void mma_bf16(float* d,
                                         uint32_t a0, uint32_t a1, uint32_t a2, uint32_t a3,
                                         uint32_t b0, uint32_t b1) {
    asm volatile(
        "mma.sync.aligned.m16n8k16.row.col.f32.bf16.bf16.f32 "
        "{%0,%1,%2,%3}, {%4,%5,%6,%7}, {%8,%9}, {%0,%1,%2,%3};"
        : "+f"(d[0]), "+f"(d[1]), "+f"(d[2]), "+f"(d[3])
        : "r"(a0), "r"(a1), "r"(a2), "r"(a3), "r"(b0), "r"(b1));
}
__device__ __forceinline__ uint32_t pack_bf16(float lo, float hi) {
    __nv_bfloat162 v = __floats2bfloat162_rn(lo, hi);
    return *reinterpret_cast<uint32_t*>(&v);
}

// ================= PA: p1_qconst (69 blocks) + p3_Mt (192 blocks) =================
__global__ void __launch_bounds__(256) pA(const float* __restrict__ mt,
                                          const float* __restrict__ W,
                                          const float* __restrict__ bias,
                                          const float* __restrict__ pw,
                                          const float* __restrict__ ow) {
    int bx = blockIdx.x;
    if (bx < 69) {
        int idx = bx*256 + threadIdx.x;   // < 17664 exactly
        int sq = idx / DD, c = idx % DD;
        const float* m = mt + sq*DD;
        const float* w = W + (size_t)c*DD;
        float acc = bias[c];
        for (int k = 0; k < DD; k++) acc += m[k]*w[k];
        g_qconst[idx] = acc * rsqrtf((float)HDD);
    } else {
        int idx = (bx - 69)*256 + threadIdx.x;   // < 49152 exactly
        int l = idx & 63;
        int d = idx >> 6;
        float acc = 0.f;
        if (l < LL) {
            const float* pr = pw + l*DD;
            for (int j = 0; j < DD; j++)
                acc += pr[j] * ow[(size_t)j*DD + d];
        }
        g_Mt[idx] = acc;
    }
}

// ================= PB: p2(576) + p4-tiled(192) + p4-tail(192) + p5a(1) + p5b(64) ====
#define PB_P2   576
#define PB_P4   (PB_P2 + 192)      // 768
#define PB_P4T  (PB_P4 + 192)      // 960
#define PB_P5A  (PB_P4T + 1)       // 961
#define PB_P5B  (PB_P5A + 64)      // 1025

__global__ void __launch_bounds__(256) pB(const float* __restrict__ W,
                                          const float* __restrict__ inb,
                                          const float* __restrict__ pw,
                                          const float* __restrict__ outb,
                                          const float* __restrict__ mt) {
    __shared__ float sh[96*64 + 96*32];   // Mt tile + W tile (36 KB)
    int bx = blockIdx.x;
    int tid = threadIdx.x;

    if (bx < PB_P2) {
        int idx = bx*256 + tid;            // < 147456 exactly
        int t = idx / DD, d = idx % DD;
        if (t >= NT) { g_sproj[idx] = 0.f; return; }
        int sq = t / HH, h = t % HH;
        const float* q = g_qconst + sq*DD + h*HDD;
        float acc = 0.f;
        for (int j = 0; j < HDD; j++)
            acc += q[j] * W[(size_t)(DD + h*HDD + j)*DD + d];
        g_sproj[idx] = acc;
    } else if (bx < PB_P4) {
        // F[h*768 + d][l] = sum_t Mt[(h*96+t)*64 + l] * Wv[(h*96+t)*768 + d]
        int b = bx - PB_P2;
        int h = b / 24, d0 = (b % 24) * 32;
        float* Mt_s = sh;                  // [96][64]
        float* W_s  = sh + 96*64;          // [96][32]
        #pragma unroll
        for (int i = 0; i < 24; i++)
            Mt_s[i*256 + tid] = g_Mt[h*96*64 + i*256 + tid];
        #pragma unroll
        for (int i = 0; i < 12; i++) {
            int f = i*256 + tid;
            int t = f >> 5, j = f & 31;
            W_s[f] = W[(size_t)(2*DD + h*HDD + t)*DD + d0 + j];
        }
        __syncthreads();
        int d = tid & 31;
        int l0 = (tid >> 5) * 8;
        float acc[8];
        #pragma unroll
        for (int q = 0; q < 8; q++) acc[q] = 0.f;
        for (int t = 0; t < 96; t++) {
            float w = W_s[t*32 + d];
            float4 m0 = *(const float4*)(Mt_s + t*64 + l0);
            float4 m1 = *(const float4*)(Mt_s + t*64 + l0 + 4);
            acc[0] += m0.x*w; acc[1] += m0.y*w; acc[2] += m0.z*w; acc[3] += m0.w*w;
            acc[4] += m1.x*w; acc[5] += m1.y*w; acc[6] += m1.z*w; acc[7] += m1.w*w;
        }
        float* dst = g_Wbig + (size_t)(h*DD + d0 + d)*NL + l0;
        *(float4*)dst = make_float4(acc[0], acc[1], acc[2], acc[3]);
        *(float4*)(dst+4) = make_float4(acc[4], acc[5], acc[6], acc[7]);
    } else if (bx < PB_P4T) {
        int idx = (bx - PB_P4)*256 + tid;  // < 49152
        int l = idx & 63;
        int kk = idx >> 6;                 // 0..767
        float v = (l < LL) ? pw[l*DD + kk] : 0.f;
        g_Wbig[(size_t)(HH*DD + kk)*NL + l] = v;
    } else if (bx < PB_P5A) {
        if (tid >= NTP) return;
        float acc = 0.f;
        if (tid < NT) {
            int sq = tid / HH, h = tid % HH;
            for (int j = 0; j < HDD; j++)
                acc += g_qconst[sq*DD + h*HDD + j] * inb[DD + h*HDD + j];
        }
        g_c0[tid] = acc;
    } else {
        int l = bx - PB_P5A;
        float a = 0.f, b2 = 0.f, c = 0.f;
        if (l < LL) {
            for (int d = tid; d < DD; d += 256) {
                float m = g_Mt[d*NL + l];
                float p = pw[l*DD + d];
                float ms = 0.f;
                #pragma unroll
                for (int s = 0; s < SS; s++) ms += mt[s*DD + d];
                a += m * inb[2*DD + d];
                b2 += p * outb[d];
                c += p * ms;
            }
        }
        #pragma unroll
        for (int o = 16; o > 0; o >>= 1) {
            a += __shfl_down_sync(0xFFFFFFFF, a, o);
            b2 += __shfl_down_sync(0xFFFFFFFF, b2, o);
            c += __shfl_down_sync(0xFFFFFFFF, c, o);
        }
        float* red = sh;    // reuse shared
        int w = tid >> 5, ln = tid & 31;
        if (ln == 0) { red[w] = a; red[8+w] = b2; red[16+w] = c; }
        __syncthreads();
        if (tid == 0) {
            float sa = 0.f, sb = 0.f, sc2 = 0.f;
            for (int i = 0; i < 8; i++) { sa += red[i]; sb += red[8+i]; sc2 += red[16+i]; }
            g_bvM[l] = sa; g_boutP[l] = sb; g_msumP[l] = sc2;
        }
    }
}

// ---------------- K1: scores GEMM via mma.sync bf16 + ldmatrix ----------------
// C[47104][192] = cls @ sproj^T + c0. CTA 64M x 192N, 256 thr / 8 warps (2m x 4n),
// warp tile 32M x 48N. K chunks of 32 bf16, double buffered. smem stride 40 half.
#define SKW 40
#define K1_ABUF 5120                    // 64*40*2 bytes per buffer
#define K1_BBUF 15360                   // 192*40*2 bytes per buffer
#define K1_BOFF (2*K1_ABUF)             // 10240
#define K1_SMEM (2*K1_ABUF + 2*K1_BBUF) // 40960
#define K1_NCHUNK 24

__global__ void __launch_bounds__(256, 2) k1_mma(const float* __restrict__ A) {
    extern __shared__ char smem[];
    uint32_t sb = smem_u32(smem);

    int tid = threadIdx.x;
    int wid = tid >> 5;
    int lane = tid & 31;
    int g = lane >> 2, t = lane & 3;
    int l16 = lane & 15, lhi = lane >> 4;
    int l8 = lane & 7, lm8 = (lane >> 3) & 1;

    int m0 = blockIdx.x * 64;
    int wm = (wid & 1) * 32;
    int wn = (wid >> 1) * 48;

    // loaders: A 64 rows x 4 segs = 256 segs (1/thread); B 192 x 4 = 768 segs (3/thread)
    int arow = tid >> 2, aq = tid & 3;
    const float* agp = A + (size_t)(m0 + arow)*DD + aq*8;
    uint32_t asts = (uint32_t)(arow*SKW + aq*8)*2;
    int br[3], bq[3];
    #pragma unroll
    for (int i = 0; i < 3; i++) { int f = i*256 + tid; br[i] = f >> 2; bq[i] = f & 3; }
    const float* bgp[3];
    uint32_t bsts[3];
    #pragma unroll
    for (int i = 0; i < 3; i++) {
        bgp[i] = g_sproj + (size_t)br[i]*DD + bq[i]*8;
        bsts[i] = (uint32_t)K1_BOFF + (uint32_t)(br[i]*SKW + bq[i]*8)*2;
    }

    uint32_t aAddr = sb + ((wm + l16)*SKW + lhi*8)*2;
    uint32_t bAddr = sb + K1_BOFF + ((wn + l8 + lhi*8)*SKW + lm8*8)*2;

    // ---- preload chunk 0 ----
    {
        float4 v0 = *(const float4*)agp;
        float4 v1 = *(const float4*)(agp + 4);
        uint4 pk;
        pk.x = pack_bf16(v0.x, v0.y); pk.y = pack_bf16(v0.z, v0.w);
        pk.z = pack_bf16(v1.x, v1.y); pk.w = pack_bf16(v1.z, v1.w);
        *(uint4*)(smem + asts) = pk;
        #pragma unroll
        for (int i = 0; i < 3; i++) {
            float4 w0 = *(const float4*)bgp[i];
            float4 w1 = *(const float4*)(bgp[i] + 4);
            pk.x = pack_bf16(w0.x, w0.y); pk.y = pack_bf16(w0.z, w0.w);
            pk.z = pack_bf16(w1.x, w1.y); pk.w = pack_bf16(w1.z, w1.w);
            *(uint4*)(smem + bsts[i]) = pk;
        }
    }
    __syncthreads();

    float acc[2][6][4];
    #pragma unroll
    for (int i = 0; i < 2; i++)
        #pragma unroll
        for (int j = 0; j < 6; j++)
            #pragma unroll
            for (int q = 0; q < 4; q++) acc[i][j][q] = 0.f;

    for (int c = 0; c < K1_NCHUNK; c++) {
        int cb = c & 1;
        bool more = (c + 1 < K1_NCHUNK);
        float4 v0, v1, w0[3], w1[3];
        if (more) {
            int kc = (c + 1) * 32;
            v0 = *(const float4*)(agp + kc);
            v1 = *(const float4*)(agp + kc + 4);
            #pragma unroll
            for (int i = 0; i < 3; i++) {
                w0[i] = *(const float4*)(bgp[i] + kc);
                w1[i] = *(const float4*)(bgp[i] + kc + 4);
            }
        }

        uint32_t aB = aAddr + cb*K1_ABUF;
        uint32_t bB = bAddr + cb*K1_BBUF;
        #pragma unroll
        for (int ks = 0; ks < 2; ks++) {
            uint32_t af[2][4];
            ldsm_x4(af[0][0], af[0][1], af[0][2], af[0][3], aB + ks*32);
            ldsm_x4(af[1][0], af[1][1], af[1][2], af[1][3], aB + 16*SKW*2 + ks*32);
            uint32_t bf[6][2];
            #pragma unroll
            for (int np = 0; np < 3; np++)
                ldsm_x4(bf[2*np][0], bf[2*np][1], bf[2*np+1][0], bf[2*np+1][1],
                        bB + np*16*SKW*2 + ks*32);
            #pragma unroll
            for (int mt = 0; mt < 2; mt++)
                #pragma unroll
                for (int nt = 0; nt < 6; nt++)
                    mma_bf16(acc[mt][nt], af[mt][0], af[mt][1], af[mt][2], af[mt][3],
                             bf[nt][0], bf[nt][1]);
        }

        if (more) {
            int nb = (c + 1) & 1;
            uint4 pk;
            pk.x = pack_bf16(v0.x, v0.y); pk.y = pack_bf16(v0.z, v0.w);
            pk.z = pack_bf16(v1.x, v1.y); pk.w = pack_bf16(v1.z, v1.w);
            *(uint4*)(smem + asts + nb*K1_ABUF) = pk;
            #pragma unroll
            for (int i = 0; i < 3; i++) {
                pk.x = pack_bf16(w0[i].x, w0[i].y); pk.y = pack_bf16(w0[i].z, w0[i].w);
                pk.z = pack_bf16(w1[i].x, w1[i].y); pk.w = pack_bf16(w1[i].z, w1[i].w);
                *(uint4*)(smem + bsts[i] + nb*K1_BBUF) = pk;
            }
            __syncthreads();
        }
    }

    // epilogue
    #pragma unroll
    for (int mt = 0; mt < 2; mt++) {
        int m = m0 + wm + mt*16 + g;
        float* row0 = g_scores + (size_t)m * NTP;
        float* row1 = row0 + 8*NTP;
        #pragma unroll
        for (int nt = 0; nt < 6; nt++) {
            int n = wn + nt*8 + 2*t;
            float c00 = g_c0[n], c01 = g_c0[n+1];
            *(float2*)(row0 + n) = make_float2(acc[mt][nt][0] + c00, acc[mt][nt][1] + c01);
            *(float2*)(row1 + n) = make_float2(acc[mt][nt][2] + c00, acc[mt][nt][3] + c01);
        }
    }
}

// ---------------- K2: per-batch softmax + u + cls_sum ----------------
__global__ void __launch_bounds__(256) k2_attn(const float* __restrict__ cls,
                                               const int* __restrict__ mask) {
    __shared__ float sc[SS][NTP];
    __shared__ float mx[NT], den[NT];
    __shared__ float wsm[HH*SS];
    __shared__ int e[SS];
    __shared__ int nex;
    int b = blockIdx.x;
    int tid = threadIdx.x;

    if (tid == 0) nex = 0;
    __syncthreads();
    if (tid < SS) {
        e[tid] = mask[b*SS + tid];
        if (e[tid]) atomicAdd(&nex, 1);
    }
    for (int idx = tid; idx < SS*NTP; idx += 256)
        sc[idx / NTP][idx % NTP] = g_scores[(size_t)b*SS*NTP + idx];
    __syncthreads();

    if (tid < NT) {
        int sq = tid / HH;
        float m = -INFINITY, d = 0.f;
        if (nex > 0 && e[sq] == 0) {
            for (int sk = 0; sk < SS; sk++)
                if (e[sk]) m = fmaxf(m, sc[sk][tid]);
            for (int sk = 0; sk < SS; sk++)
                if (e[sk]) d += __expf(sc[sk][tid] - m);
        }
        mx[tid] = m; den[tid] = d;
    }
    __syncthreads();

    if (tid < HH*SS) {
        int h = tid / SS, sk = tid % SS;
        float w = 0.f;
        if (nex > 0 && e[sk]) {
            for (int sq = 0; sq < SS; sq++) {
                if (e[sq] == 0) {
                    int t = sq*HH + h;
                    w += __expf(sc[sk][t] - mx[t]) / den[t];
                }
            }
        }
        wsm[tid] = w;
    }
    __syncthreads();

    float* arow = g_A + (size_t)b * KA;
    for (int d0 = tid; d0 < DD; d0 += 256) {
        float u[HH];
        #pragma unroll
        for (int h = 0; h < HH; h++) u[h] = 0.f;
        float csum = 0.f;
        for (int sk = 0; sk < SS; sk++) {
            float c = cls[((size_t)b*SS + sk)*DD + d0];
            if (e[sk]) {
                csum += c;
                #pragma unroll
                for (int h = 0; h < HH; h++) u[h] += wsm[h*SS + sk] * c;
            }
        }
        #pragma unroll
        for (int h = 0; h < HH; h++) arow[h*DD + d0] = u[h];
        arow[HH*DD + d0] = csum;
    }
}

// ---------------- K3a: split-K logits GEMM ----------------
__global__ void __launch_bounds__(256) k3_gemm() {
    __shared__ float As[2][8][132];
    __shared__ float Bs[2][8][68];
    int tid = threadIdx.x;
    int m0 = blockIdx.x * 128;
    int split = blockIdx.y;
    int k0 = split * 768;
    int ty = tid >> 4, tx = tid & 15;
    int arow = tid >> 1, acol = (tid & 1) * 4;
    int bk = tid >> 5, bn = (tid & 31) * 2;

    const float* aptr = g_A + (size_t)(m0 + arow)*KA + k0 + acol;
    const float* bptr = g_Wbig + (size_t)(k0 + bk)*NL + bn;

    {
        float4 av = *(const float4*)aptr;
        As[0][acol+0][arow] = av.x; As[0][acol+1][arow] = av.y;
        As[0][acol+2][arow] = av.z; As[0][acol+3][arow] = av.w;
        float2 bv = *(const float2*)bptr;
        Bs[0][bk][bn+0] = bv.x; Bs[0][bk][bn+1] = bv.y;
    }
    __syncthreads();

    float acc[8][4];
    #pragma unroll
    for (int i = 0; i < 8; i++)
        #pragma unroll
        for (int j = 0; j < 4; j++) acc[i][j] = 0.f;

    const int NK = 768 / 8;
    for (int kt = 0; kt < NK; kt++) {
        int cur = kt & 1, nxt = cur ^ 1;
        float4 av; float2 bv;
        bool more = (kt + 1 < NK);
        if (more) {
            av = *(const float4*)(aptr + (kt+1)*8);
            bv = *(const float2*)(bptr + (size_t)(kt+1)*8*NL);
        }
        #pragma unroll
        for (int kk = 0; kk < 8; kk++) {
            float4 a0 = *(const float4*)&As[cur][kk][ty*8];
            float4 a1 = *(const float4*)&As[cur][kk][ty*8 + 4];
            float4 b0 = *(const float4*)&Bs[cur][kk][tx*4];
            float a[8] = {a0.x,a0.y,a0.z,a0.w,a1.x,a1.y,a1.z,a1.w};
            float b[4] = {b0.x,b0.y,b0.z,b0.w};
            #pragma unroll
            for (int i = 0; i < 8; i++)
                #pragma unroll
                for (int j = 0; j < 4; j++) acc[i][j] += a[i]*b[j];
        }
        if (more) {
            As[nxt][acol+0][arow] = av.x; As[nxt][acol+1][arow] = av.y;
            As[nxt][acol+2][arow] = av.z; As[nxt][acol+3][arow] = av.w;
            Bs[nxt][bk][bn+0] = bv.x; Bs[nxt][bk][bn+1] = bv.y;
            __syncthreads();
        }
    }

    #pragma unroll
    for (int i = 0; i < 8; i++) {
        int m = m0 + ty*8 + i;
        #pragma unroll
        for (int j = 0; j < 4; j++) {
            int n = tx*4 + j;
            g_P[((size_t)split*BB + m)*NL + n] = acc[i][j];
        }
    }
}

// ---------------- K3b: reduce splits + scalar terms + degenerate path ----------------
__global__ void k3b_final(const int* __restrict__ mask, const float* __restrict__ pb,
                          float* __restrict__ out) {
    int idx = blockIdx.x*256 + threadIdx.x;
    if (idx >= BB*NL) return;
    int b = idx / NL, l = idx % NL;
    if (l >= LL) return;
    int nex = 0;
    for (int s = 0; s < SS; s++) nex += (mask[b*SS + s] != 0);
    float r;
    if (nex > 0) {
        float acc = 0.f;
        for (int s = 0; s < NSPLIT; s++)
            acc += g_P[((size_t)s*BB + b)*NL + l];
        float nmiss = (float)(SS - nex);
        r = (acc + nmiss*(g_bvM[l] + g_boutP[l])) * (1.f/SS) + pb[l];
    } else {
        r = g_msumP[l] * (1.f/SS) + pb[l];
    }
    out[b*LL + l] = r;
}

// ---------------- launcher ----------------
extern "C" void kernel_launch(void* const* d_in, const int* in_sizes, int n_in,
                              void* d_out, int out_size) {
    const float* cls  = (const float*)d_in[0];
    const int*   mask = (const int*)  d_in[1];
    const float* mt   = (const float*)d_in[2];
    const float* ipw  = (const float*)d_in[3];
    const float* ipb  = (const float*)d_in[4];
    const float* opw  = (const float*)d_in[5];
    const float* opb  = (const float*)d_in[6];
    const float* pw   = (const float*)d_in[7];
    const float* pb   = (const float*)d_in[8];
    float* out = (float*)d_out;

    pA<<<261, 256>>>(mt, ipw, ipb, pw, opw);
    pB<<<PB_P5B, 256>>>(ipw, ipb, pw, opb, mt);

    k1_mma<<<736, 256, K1_SMEM>>>(cls);
    k2_attn<<<BB, 256>>>(cls, mask);
    dim3 g3(16, NSPLIT);
    k3_gemm<<<g3, 256>>>();
    k3b_final<<<(BB*NL + 255)/256, 256>>>(mask, pb, out);
}